// round 3
// baseline (speedup 1.0000x reference)
#include <cuda_runtime.h>
#include <cstdint>

#define NN      100000
#define IN_DIM  512
#define HIDDEN  128
#define NCLS    64
#define NEDGE   3200000

// ---------------- device scratch (allocation-free) ----------------
__device__ float g_h[(size_t)NN * HIDDEN];      // relu(X@W0)
__device__ float g_bufA[(size_t)NN * NCLS];     // dense out
__device__ float g_bufB[(size_t)NN * NCLS];     // after 1st spmm
__device__ int   g_ssrc[NEDGE];                 // sorted-by-dst src
__device__ float g_sval[NEDGE];                 // sorted-by-dst val
__device__ int   g_cnt[NN];
__device__ int   g_tmp[NN];
__device__ int   g_rp[NN + 1];
__device__ int   g_cur[NN];
__device__ int   g_bsum[512];
__device__ int   g_boff[512];

// ---------------------------------------------------------------------------
// GEMM1: H = relu(X[N,512] @ W0[512,128]); 128x128 tile, BK=16, 256 thr,
// 8x8 microtile, register-prefetch. Small smem -> 2 CTAs/SM.
// ---------------------------------------------------------------------------
#define BM 128
#define BK 16
#define AS_PITCH 136

__global__ __launch_bounds__(256, 2)
void gemm1(const float* __restrict__ X, const float* __restrict__ W0,
           float* __restrict__ H)
{
    __shared__ float As[BK * AS_PITCH];
    __shared__ float Bs[BK * HIDDEN];

    const int tid = threadIdx.x;
    const int bm  = blockIdx.x * BM;

    const int tr = tid >> 4;
    const int tc = tid & 15;
    const int r0 = tr * 8;
    const int c0 = tc * 4;
    const int c1 = 64 + tc * 4;

    const int a_row = tid >> 2;
    const int a_k4  = (tid & 3) * 4;
    int grow0 = bm + a_row;       if (grow0 >= NN) grow0 = NN - 1;
    int grow1 = bm + a_row + 64;  if (grow1 >= NN) grow1 = NN - 1;

    float acc[8][8];
    #pragma unroll
    for (int i = 0; i < 8; i++)
        #pragma unroll
        for (int j = 0; j < 8; j++) acc[i][j] = 0.f;

    float4 pa0 = *(const float4*)&X[(size_t)grow0 * IN_DIM + a_k4];
    float4 pa1 = *(const float4*)&X[(size_t)grow1 * IN_DIM + a_k4];
    float4 pb0 = *(const float4*)&W0[(size_t)(tid >> 5) * HIDDEN + (tid & 31) * 4];
    float4 pb1 = *(const float4*)&W0[(size_t)((tid + 256) >> 5) * HIDDEN + ((tid + 256) & 31) * 4];

    const int NKT = IN_DIM / BK;   // 32
    for (int kt = 0; kt < NKT; kt++) {
        As[(a_k4 + 0) * AS_PITCH + a_row] = pa0.x;
        As[(a_k4 + 1) * AS_PITCH + a_row] = pa0.y;
        As[(a_k4 + 2) * AS_PITCH + a_row] = pa0.z;
        As[(a_k4 + 3) * AS_PITCH + a_row] = pa0.w;
        As[(a_k4 + 0) * AS_PITCH + a_row + 64] = pa1.x;
        As[(a_k4 + 1) * AS_PITCH + a_row + 64] = pa1.y;
        As[(a_k4 + 2) * AS_PITCH + a_row + 64] = pa1.z;
        As[(a_k4 + 3) * AS_PITCH + a_row + 64] = pa1.w;
        *(float4*)&Bs[(tid >> 5) * HIDDEN + (tid & 31) * 4] = pb0;
        *(float4*)&Bs[((tid + 256) >> 5) * HIDDEN + ((tid + 256) & 31) * 4] = pb1;
        __syncthreads();

        if (kt + 1 < NKT) {
            const int kb = (kt + 1) * BK;
            pa0 = *(const float4*)&X[(size_t)grow0 * IN_DIM + kb + a_k4];
            pa1 = *(const float4*)&X[(size_t)grow1 * IN_DIM + kb + a_k4];
            pb0 = *(const float4*)&W0[(size_t)(kb + (tid >> 5)) * HIDDEN + (tid & 31) * 4];
            pb1 = *(const float4*)&W0[(size_t)(kb + ((tid + 256) >> 5)) * HIDDEN + ((tid + 256) & 31) * 4];
        }

        #pragma unroll
        for (int k = 0; k < BK; k++) {
            float4 a0 = *(const float4*)&As[k * AS_PITCH + r0];
            float4 a1 = *(const float4*)&As[k * AS_PITCH + r0 + 4];
            float4 b0 = *(const float4*)&Bs[k * HIDDEN + c0];
            float4 b1 = *(const float4*)&Bs[k * HIDDEN + c1];
            float av[8] = {a0.x, a0.y, a0.z, a0.w, a1.x, a1.y, a1.z, a1.w};
            #pragma unroll
            for (int i = 0; i < 8; i++) {
                acc[i][0] += av[i] * b0.x;
                acc[i][1] += av[i] * b0.y;
                acc[i][2] += av[i] * b0.z;
                acc[i][3] += av[i] * b0.w;
                acc[i][4] += av[i] * b1.x;
                acc[i][5] += av[i] * b1.y;
                acc[i][6] += av[i] * b1.z;
                acc[i][7] += av[i] * b1.w;
            }
        }
        __syncthreads();
    }

    // ReLU + store to H
    #pragma unroll
    for (int i = 0; i < 8; i++) {
        const int m = bm + r0 + i;
        if (m < NN) {
            float4 lo = {fmaxf(acc[i][0], 0.f), fmaxf(acc[i][1], 0.f),
                         fmaxf(acc[i][2], 0.f), fmaxf(acc[i][3], 0.f)};
            float4 hi = {fmaxf(acc[i][4], 0.f), fmaxf(acc[i][5], 0.f),
                         fmaxf(acc[i][6], 0.f), fmaxf(acc[i][7], 0.f)};
            *(float4*)&H[(size_t)m * HIDDEN + c0] = lo;
            *(float4*)&H[(size_t)m * HIDDEN + c1] = hi;
        }
    }
}

// ---------------------------------------------------------------------------
// GEMM2: O = H[N,128] @ W1[128,64]. 64-row tiles, 256 thr, 4x4 microtile.
// Memory-bound (~77MB); dynamic smem 66.5KB.
// ---------------------------------------------------------------------------
#define BM2 64
#define HT2_PITCH 132
#define G2_SMEM_FLOATS (HIDDEN * NCLS + BM2 * HT2_PITCH)
#define G2_SMEM_BYTES  (G2_SMEM_FLOATS * 4)

__global__ __launch_bounds__(256)
void gemm2(const float* __restrict__ H, const float* __restrict__ W1,
           float* __restrict__ O)
{
    extern __shared__ float sm2[];
    float* W1s = sm2;                    // [128][64]
    float* Hs  = sm2 + HIDDEN * NCLS;    // [64][132]

    const int tid = threadIdx.x;
    const int bm  = blockIdx.x * BM2;

    // load W1 (2048 float4)
    {
        const float4* w1v = (const float4*)W1;
        float4* w1sv = (float4*)W1s;
        #pragma unroll
        for (int i = 0; i < 8; i++)
            w1sv[tid + i * 256] = w1v[tid + i * 256];
    }
    // load H tile 64x128 (2048 float4), store with pitch 132
    #pragma unroll
    for (int j = 0; j < 8; j++) {
        int f = tid + j * 256;
        int row = f >> 5;
        int k4  = (f & 31) * 4;
        int gr = bm + row; if (gr >= NN) gr = NN - 1;
        float4 v = *(const float4*)&H[(size_t)gr * HIDDEN + k4];
        *(float4*)&Hs[row * HT2_PITCH + k4] = v;
    }
    __syncthreads();

    const int tr = tid >> 4;
    const int tc = tid & 15;
    const int r0 = tr * 4;
    const int c0 = tc * 4;

    float acc[4][4];
    #pragma unroll
    for (int i = 0; i < 4; i++)
        #pragma unroll
        for (int j = 0; j < 4; j++) acc[i][j] = 0.f;

    #pragma unroll 4
    for (int k = 0; k < HIDDEN; k += 4) {
        float4 a[4], b[4];
        #pragma unroll
        for (int i = 0; i < 4; i++)
            a[i] = *(const float4*)&Hs[(r0 + i) * HT2_PITCH + k];
        #pragma unroll
        for (int kk = 0; kk < 4; kk++)
            b[kk] = *(const float4*)&W1s[(k + kk) * NCLS + c0];
        #pragma unroll
        for (int i = 0; i < 4; i++) {
            acc[i][0] += a[i].x * b[0].x + a[i].y * b[1].x + a[i].z * b[2].x + a[i].w * b[3].x;
            acc[i][1] += a[i].x * b[0].y + a[i].y * b[1].y + a[i].z * b[2].y + a[i].w * b[3].y;
            acc[i][2] += a[i].x * b[0].z + a[i].y * b[1].z + a[i].z * b[2].z + a[i].w * b[3].z;
            acc[i][3] += a[i].x * b[0].w + a[i].y * b[1].w + a[i].z * b[2].w + a[i].w * b[3].w;
        }
    }

    #pragma unroll
    for (int i = 0; i < 4; i++) {
        const int m = bm + r0 + i;
        if (m < NN) {
            float4 v = {acc[i][0], acc[i][1], acc[i][2], acc[i][3]};
            *(float4*)&O[(size_t)m * NCLS + c0] = v;
        }
    }
}

// ---------------------------------------------------------------------------
// Counting sort of edges by dst -> CSR
// ---------------------------------------------------------------------------
__global__ void k_hist(const int* __restrict__ dst)
{
    int base = blockIdx.x * 1024 + threadIdx.x;
    #pragma unroll
    for (int j = 0; j < 4; j++) {
        int e = base + j * 256;
        if (e < NEDGE) atomicAdd(&g_cnt[dst[e]], 1);
    }
}

__global__ void k_scan_local()   // per-256 chunk inclusive scan + block sums
{
    __shared__ int s[256];
    int t = threadIdx.x;
    int i = blockIdx.x * 256 + t;
    int v = (i < NN) ? g_cnt[i] : 0;
    s[t] = v;
    __syncthreads();
    int x = v;
    #pragma unroll
    for (int off = 1; off < 256; off <<= 1) {
        int y = (t >= off) ? s[t - off] : 0;
        __syncthreads();
        x += y;
        s[t] = x;
        __syncthreads();
    }
    if (i < NN) g_tmp[i] = x;
    if (t == 255) g_bsum[blockIdx.x] = x;
}

__global__ void k_scan_block(int nb)   // single block, 512 thr
{
    __shared__ int s[512];
    int t = threadIdx.x;
    int v = (t < nb) ? g_bsum[t] : 0;
    s[t] = v;
    __syncthreads();
    int x = v;
    #pragma unroll
    for (int off = 1; off < 512; off <<= 1) {
        int y = (t >= off) ? s[t - off] : 0;
        __syncthreads();
        x += y;
        s[t] = x;
        __syncthreads();
    }
    g_boff[t] = x - v;   // exclusive
}

__global__ void k_scan_final()
{
    int i = blockIdx.x * 256 + threadIdx.x;
    if (i < NN) {
        int e = g_tmp[i] - g_cnt[i] + g_boff[blockIdx.x];  // exclusive prefix
        g_rp[i]  = e;
        g_cur[i] = e;
    }
    if (i == 0) g_rp[NN] = NEDGE;
}

__global__ void k_scatter(const int* __restrict__ src,
                          const int* __restrict__ dst,
                          const float* __restrict__ val)
{
    int base = blockIdx.x * 1024 + threadIdx.x;
    #pragma unroll
    for (int j = 0; j < 4; j++) {
        int e = base + j * 256;
        if (e < NEDGE) {
            int d = dst[e];
            int p = atomicAdd(&g_cur[d], 1);
            g_ssrc[p] = src[e];
            g_sval[p] = val[e];
        }
    }
}

// ---------------------------------------------------------------------------
// CSR SpMM: one warp per dst row; lane handles float2 of the 64 features.
// ---------------------------------------------------------------------------
__global__ __launch_bounds__(256)
void spmm_csr(const float* __restrict__ x, float* __restrict__ y)
{
    const int wg   = (blockIdx.x * blockDim.x + threadIdx.x) >> 5;
    const int lane = threadIdx.x & 31;
    if (wg >= NN) return;

    const int start = __ldg(&g_rp[wg]);
    const int end   = __ldg(&g_rp[wg + 1]);
    const float2* xs = (const float2*)x;

    float2 acc = {0.f, 0.f};
    int e = start;
    for (; e + 4 <= end; e += 4) {
        int   s0 = g_ssrc[e],     s1 = g_ssrc[e + 1];
        int   s2 = g_ssrc[e + 2], s3 = g_ssrc[e + 3];
        float v0 = g_sval[e],     v1 = g_sval[e + 1];
        float v2 = g_sval[e + 2], v3 = g_sval[e + 3];
        float2 a0 = xs[(size_t)s0 * 32 + lane];
        float2 a1 = xs[(size_t)s1 * 32 + lane];
        float2 a2 = xs[(size_t)s2 * 32 + lane];
        float2 a3 = xs[(size_t)s3 * 32 + lane];
        acc.x += v0 * a0.x + v1 * a1.x + v2 * a2.x + v3 * a3.x;
        acc.y += v0 * a0.y + v1 * a1.y + v2 * a2.y + v3 * a3.y;
    }
    for (; e < end; e++) {
        int   s = g_ssrc[e];
        float v = g_sval[e];
        float2 a = xs[(size_t)s * 32 + lane];
        acc.x += v * a.x;
        acc.y += v * a.y;
    }
    ((float2*)y)[(size_t)wg * 32 + lane] = acc;
}

// ---------------------------------------------------------------------------
extern "C" void kernel_launch(void* const* d_in, const int* in_sizes, int n_in,
                              void* d_out, int out_size)
{
    const float* X  = (const float*)d_in[0];
    const float* W0 = (const float*)d_in[1];
    const float* W1 = (const float*)d_in[2];
    const float* ev = (const float*)d_in[3];
    const int*   es = (const int*)d_in[4];
    const int*   ed = (const int*)d_in[5];
    float* out = (float*)d_out;

    float *h, *bufA, *bufB;
    int *cnt;
    cudaGetSymbolAddress((void**)&h,    g_h);
    cudaGetSymbolAddress((void**)&bufA, g_bufA);
    cudaGetSymbolAddress((void**)&bufB, g_bufB);
    cudaGetSymbolAddress((void**)&cnt,  g_cnt);

    cudaFuncSetAttribute(gemm2, cudaFuncAttributeMaxDynamicSharedMemorySize,
                         G2_SMEM_BYTES);

    const int NB_SCAN = (NN + 255) / 256;          // 391
    const int EB      = (NEDGE + 1023) / 1024;     // 3125

    // dense phase
    gemm1<<<(NN + BM - 1) / BM, 256>>>(X, W0, h);
    gemm2<<<(NN + BM2 - 1) / BM2, 256, G2_SMEM_BYTES>>>(h, W1, bufA);

    // build CSR (independent of dense phase)
    cudaMemsetAsync(cnt, 0, NN * sizeof(int));
    k_hist<<<EB, 256>>>(ed);
    k_scan_local<<<NB_SCAN, 256>>>();
    k_scan_block<<<1, 512>>>(NB_SCAN);
    k_scan_final<<<NB_SCAN, 256>>>();
    k_scatter<<<EB, 256>>>(es, ed, ev);

    // graph phase
    const int CSR_GRID = (NN * 32 + 255) / 256;    // 12500
    spmm_csr<<<CSR_GRID, 256>>>(bufA, bufB);
    spmm_csr<<<CSR_GRID, 256>>>(bufB, out);
}

// round 5
// speedup vs baseline: 1.3839x; 1.3839x over previous
#include <cuda_runtime.h>
#include <cstdint>

#define NN      100000
#define IN_DIM  512
#define HIDDEN  128
#define NCLS    64
#define NEDGE   3200000

// ---------------- device scratch (allocation-free) ----------------
__device__ float g_h[(size_t)NN * HIDDEN];      // relu(X@W0)
__device__ float g_bufA[(size_t)NN * NCLS];     // dense out
__device__ float g_bufB[(size_t)NN * NCLS];     // after 1st spmm

// ---------------------------------------------------------------------------
// GEMM1: H = relu(X[N,512] @ W0[512,128])
// 128x128 tile, BK=8, 256 threads, 8x8 microtile, register prefetch.
// Low smem (8.6KB) + ~100 regs -> true 2 CTAs/SM.
// ---------------------------------------------------------------------------
#define BM 128
#define BK 8
#define AS_PITCH 136

__global__ __launch_bounds__(256, 2)
void gemm1(const float* __restrict__ X, const float* __restrict__ W0,
           float* __restrict__ H)
{
    __shared__ float As[BK * AS_PITCH];   // [k][row], transposed
    __shared__ float Bs[BK * HIDDEN];     // [k][col]

    const int tid = threadIdx.x;
    const int bm  = blockIdx.x * BM;

    // microtile mapping
    const int tr = tid >> 4;        // 0..15
    const int tc = tid & 15;        // 0..15
    const int r0 = tr * 8;
    const int c0 = tc * 4;
    const int c1 = 64 + tc * 4;

    // A load: 128 rows x 8 k = 256 float4; thread t -> row t>>1, k4 (t&1)*4
    const int a_row = tid >> 1;
    const int a_k4  = (tid & 1) * 4;
    int grow = bm + a_row; if (grow >= NN) grow = NN - 1;

    // B load: 8 k x 128 cols = 256 float4; thread t -> k t>>5, c4 (t&31)*4
    const int b_k  = tid >> 5;
    const int b_c4 = (tid & 31) * 4;

    float acc[8][8];
    #pragma unroll
    for (int i = 0; i < 8; i++)
        #pragma unroll
        for (int j = 0; j < 8; j++) acc[i][j] = 0.f;

    // prologue prefetch
    float4 pa = *(const float4*)&X[(size_t)grow * IN_DIM + a_k4];
    float4 pb = *(const float4*)&W0[(size_t)b_k * HIDDEN + b_c4];

    const int NKT = IN_DIM / BK;   // 64
    for (int kt = 0; kt < NKT; kt++) {
        As[(a_k4 + 0) * AS_PITCH + a_row] = pa.x;
        As[(a_k4 + 1) * AS_PITCH + a_row] = pa.y;
        As[(a_k4 + 2) * AS_PITCH + a_row] = pa.z;
        As[(a_k4 + 3) * AS_PITCH + a_row] = pa.w;
        *(float4*)&Bs[b_k * HIDDEN + b_c4] = pb;
        __syncthreads();

        if (kt + 1 < NKT) {
            const int kb = (kt + 1) * BK;
            pa = *(const float4*)&X[(size_t)grow * IN_DIM + kb + a_k4];
            pb = *(const float4*)&W0[(size_t)(kb + b_k) * HIDDEN + b_c4];
        }

        #pragma unroll
        for (int k = 0; k < BK; k++) {
            float4 a0 = *(const float4*)&As[k * AS_PITCH + r0];
            float4 a1 = *(const float4*)&As[k * AS_PITCH + r0 + 4];
            float4 b0 = *(const float4*)&Bs[k * HIDDEN + c0];
            float4 b1 = *(const float4*)&Bs[k * HIDDEN + c1];
            float av[8] = {a0.x, a0.y, a0.z, a0.w, a1.x, a1.y, a1.z, a1.w};
            #pragma unroll
            for (int i = 0; i < 8; i++) {
                acc[i][0] += av[i] * b0.x;
                acc[i][1] += av[i] * b0.y;
                acc[i][2] += av[i] * b0.z;
                acc[i][3] += av[i] * b0.w;
                acc[i][4] += av[i] * b1.x;
                acc[i][5] += av[i] * b1.y;
                acc[i][6] += av[i] * b1.z;
                acc[i][7] += av[i] * b1.w;
            }
        }
        __syncthreads();
    }

    // ReLU + store
    #pragma unroll
    for (int i = 0; i < 8; i++) {
        const int m = bm + r0 + i;
        if (m < NN) {
            float4 lo = {fmaxf(acc[i][0], 0.f), fmaxf(acc[i][1], 0.f),
                         fmaxf(acc[i][2], 0.f), fmaxf(acc[i][3], 0.f)};
            float4 hi = {fmaxf(acc[i][4], 0.f), fmaxf(acc[i][5], 0.f),
                         fmaxf(acc[i][6], 0.f), fmaxf(acc[i][7], 0.f)};
            *(float4*)&H[(size_t)m * HIDDEN + c0] = lo;
            *(float4*)&H[(size_t)m * HIDDEN + c1] = hi;
        }
    }
}

// ---------------------------------------------------------------------------
// GEMM2: O = H[N,128] @ W1[128,64]. 64-row tiles, 256 thr, 4x4 microtile.
// Memory-bound (~77MB traffic).
// ---------------------------------------------------------------------------
#define BM2 64
#define HT2_PITCH 132
#define G2_SMEM_FLOATS (HIDDEN * NCLS + BM2 * HT2_PITCH)
#define G2_SMEM_BYTES  (G2_SMEM_FLOATS * 4)

__global__ __launch_bounds__(256)
void gemm2(const float* __restrict__ H, const float* __restrict__ W1,
           float* __restrict__ O)
{
    extern __shared__ float sm2[];
    float* W1s = sm2;                    // [128][64]
    float* Hs  = sm2 + HIDDEN * NCLS;    // [64][132]

    const int tid = threadIdx.x;
    const int bm  = blockIdx.x * BM2;

    {
        const float4* w1v = (const float4*)W1;
        float4* w1sv = (float4*)W1s;
        #pragma unroll
        for (int i = 0; i < 8; i++)
            w1sv[tid + i * 256] = w1v[tid + i * 256];
    }
    #pragma unroll
    for (int j = 0; j < 8; j++) {
        int f = tid + j * 256;
        int row = f >> 5;
        int k4  = (f & 31) * 4;
        int gr = bm + row; if (gr >= NN) gr = NN - 1;
        float4 v = *(const float4*)&H[(size_t)gr * HIDDEN + k4];
        *(float4*)&Hs[row * HT2_PITCH + k4] = v;
    }
    __syncthreads();

    const int tr = tid >> 4;
    const int tc = tid & 15;
    const int r0 = tr * 4;
    const int c0 = tc * 4;

    float acc[4][4];
    #pragma unroll
    for (int i = 0; i < 4; i++)
        #pragma unroll
        for (int j = 0; j < 4; j++) acc[i][j] = 0.f;

    #pragma unroll 4
    for (int k = 0; k < HIDDEN; k += 4) {
        float4 a[4], b[4];
        #pragma unroll
        for (int i = 0; i < 4; i++)
            a[i] = *(const float4*)&Hs[(r0 + i) * HT2_PITCH + k];
        #pragma unroll
        for (int kk = 0; kk < 4; kk++)
            b[kk] = *(const float4*)&W1s[(k + kk) * NCLS + c0];
        #pragma unroll
        for (int i = 0; i < 4; i++) {
            acc[i][0] += a[i].x * b[0].x + a[i].y * b[1].x + a[i].z * b[2].x + a[i].w * b[3].x;
            acc[i][1] += a[i].x * b[0].y + a[i].y * b[1].y + a[i].z * b[2].y + a[i].w * b[3].y;
            acc[i][2] += a[i].x * b[0].z + a[i].y * b[1].z + a[i].z * b[2].z + a[i].w * b[3].z;
            acc[i][3] += a[i].x * b[0].w + a[i].y * b[1].w + a[i].z * b[2].w + a[i].w * b[3].w;
        }
    }

    #pragma unroll
    for (int i = 0; i < 4; i++) {
        const int m = bm + r0 + i;
        if (m < NN) {
            float4 v = {acc[i][0], acc[i][1], acc[i][2], acc[i][3]};
            *(float4*)&O[(size_t)m * NCLS + c0] = v;
        }
    }
}

// ---------------------------------------------------------------------------
// SpMM: y[dst] += val * x[src]. 16 threads/edge, vector red.global.add.v4.f32.
// (Round-1 proven form: ~135us per layer, LTS-cap bound.)
// ---------------------------------------------------------------------------
#define EDGE_ITER 4

__device__ __forceinline__ void red_add_v4(float* addr, float4 v) {
    asm volatile("red.global.add.v4.f32 [%0], {%1,%2,%3,%4};"
                 :: "l"(addr), "f"(v.x), "f"(v.y), "f"(v.z), "f"(v.w)
                 : "memory");
}

__global__ __launch_bounds__(256)
void spmm_kernel(const int* __restrict__ src,
                 const int* __restrict__ dst,
                 const float* __restrict__ val,
                 const float* __restrict__ x,
                 float* __restrict__ y)
{
    const unsigned tid = blockIdx.x * blockDim.x + threadIdx.x;
    const unsigned g = tid >> 4;          // edge group
    const unsigned p = (tid & 15) * 4;    // feature offset
    unsigned e = g * EDGE_ITER;
    #pragma unroll
    for (int it = 0; it < EDGE_ITER; it++, e++) {
        if (e < NEDGE) {
            const int   s = __ldg(src + e);
            const int   d = __ldg(dst + e);
            const float v = __ldg(val + e);
            float4 xv = *(const float4*)(x + (size_t)s * NCLS + p);
            xv.x *= v; xv.y *= v; xv.z *= v; xv.w *= v;
            red_add_v4(y + (size_t)d * NCLS + p, xv);
        }
    }
}

// ---------------------------------------------------------------------------
extern "C" void kernel_launch(void* const* d_in, const int* in_sizes, int n_in,
                              void* d_out, int out_size)
{
    const float* X  = (const float*)d_in[0];
    const float* W0 = (const float*)d_in[1];
    const float* W1 = (const float*)d_in[2];
    const float* ev = (const float*)d_in[3];
    const int*   es = (const int*)d_in[4];
    const int*   ed = (const int*)d_in[5];
    float* out = (float*)d_out;

    float *h, *bufA, *bufB;
    cudaGetSymbolAddress((void**)&h,    g_h);
    cudaGetSymbolAddress((void**)&bufA, g_bufA);
    cudaGetSymbolAddress((void**)&bufB, g_bufB);

    cudaFuncSetAttribute(gemm2, cudaFuncAttributeMaxDynamicSharedMemorySize,
                         G2_SMEM_BYTES);

    const size_t feat_bytes = (size_t)NN * NCLS * sizeof(float);
    const int spmm_grid = (int)(((size_t)NEDGE * 16) / (256 * EDGE_ITER)); // 50000

    // zero accumulators up front (independent of dense phase)
    cudaMemsetAsync(bufB, 0, feat_bytes);
    cudaMemsetAsync(out, 0, feat_bytes);

    // dense phase
    gemm1<<<(NN + BM - 1) / BM, 256>>>(X, W0, h);
    gemm2<<<(NN + BM2 - 1) / BM2, 256, G2_SMEM_BYTES>>>(h, W1, bufA);

    // graph phase
    spmm_kernel<<<spmm_grid, 256>>>(es, ed, ev, bufA, bufB);
    spmm_kernel<<<spmm_grid, 256>>>(es, ed, ev, bufB, out);
}

// round 7
// speedup vs baseline: 1.6325x; 1.1796x over previous
#include <cuda_runtime.h>
#include <cuda_bf16.h>
#include <cstdint>

#define NN      100000
#define IN_DIM  512
#define HIDDEN  128
#define NCLS    64
#define NEDGE   3200000

// ---------------- device scratch (allocation-free) ----------------
__device__ float g_h[(size_t)NN * HIDDEN];      // relu(X@W0)
__device__ float g_bufA[(size_t)NN * NCLS];     // dense out
__device__ float g_bufB[(size_t)NN * NCLS];     // after 1st spmm
__device__ __nv_bfloat16 g_w0hi[IN_DIM * HIDDEN];  // W0^T as [n][k], hi part
__device__ __nv_bfloat16 g_w0lo[IN_DIM * HIDDEN];  // W0^T as [n][k], lo part

// ---------------------------------------------------------------------------
// W0 transpose + bf16 hi/lo split: [k][n] fp32 -> [n][k] bf16 x2. 65536 elems.
// ---------------------------------------------------------------------------
__global__ void w0_conv(const float* __restrict__ W0)
{
    int i = blockIdx.x * 256 + threadIdx.x;     // i = n*512 + k
    int n = i >> 9;
    int k = i & 511;
    float v = W0[k * HIDDEN + n];
    __nv_bfloat16 hi = __float2bfloat16(v);
    g_w0hi[i] = hi;
    g_w0lo[i] = __float2bfloat16(v - __bfloat162float(hi));
}

// ---------------------------------------------------------------------------
// GEMM1 via tensor cores: H = relu(X[N,512] @ W0[512,128])
// mma.sync.m16n8k16 bf16, hi/lo split (3 mmas per tile-product).
// Block 128x128, BK=32, 8 warps (4M x 2N), warp tile 32x64.
// ---------------------------------------------------------------------------
#define ASTRIDE 40   // bf16 elements per smem row (80B = 20 banks: frag-LDS conflict-free)

__device__ __forceinline__ uint32_t pack_bf16x2(float a, float b)
{
    __nv_bfloat162 h = __floats2bfloat162_rn(a, b);
    return *(uint32_t*)&h;
}

__device__ __forceinline__ void mma16816(float* d, const uint32_t* a,
                                         uint32_t b0, uint32_t b1)
{
    asm("mma.sync.aligned.m16n8k16.row.col.f32.bf16.bf16.f32 "
        "{%0,%1,%2,%3}, {%4,%5,%6,%7}, {%8,%9}, {%0,%1,%2,%3};"
        : "+f"(d[0]), "+f"(d[1]), "+f"(d[2]), "+f"(d[3])
        : "r"(a[0]), "r"(a[1]), "r"(a[2]), "r"(a[3]), "r"(b0), "r"(b1));
}

__global__ __launch_bounds__(256)
void gemm1_mma(const float* __restrict__ X,
               const __nv_bfloat16* __restrict__ Whi,
               const __nv_bfloat16* __restrict__ Wlo,
               float* __restrict__ H)
{
    __shared__ __nv_bfloat16 Ahi[128 * ASTRIDE];
    __shared__ __nv_bfloat16 Alo[128 * ASTRIDE];
    __shared__ __nv_bfloat16 Bhi[128 * ASTRIDE];
    __shared__ __nv_bfloat16 Blo[128 * ASTRIDE];

    const int tid    = threadIdx.x;
    const int lane   = tid & 31;
    const int wid    = tid >> 5;
    const int warp_m = wid >> 1;       // 0..3
    const int warp_n = wid & 1;        // 0..1
    const int bm     = blockIdx.x * 128;

    // A loader: thread -> (row, khalf). 128 rows x 2 halves = 256 threads.
    const int a_row = tid >> 1;
    const int a_kh  = (tid & 1) * 16;
    int grow = bm + a_row; if (grow >= NN) grow = NN - 1;
    const float* Xp = X + (size_t)grow * IN_DIM + a_kh;

    // B loader: thread -> (n, khalf). 128 n x 2 halves.
    const int b_n = tid >> 1;
    const __nv_bfloat16* Whip = Whi + (size_t)b_n * IN_DIM + a_kh;
    const __nv_bfloat16* Wlop = Wlo + (size_t)b_n * IN_DIM + a_kh;

    float acc[2][8][4];
    #pragma unroll
    for (int mt = 0; mt < 2; mt++)
        #pragma unroll
        for (int nt = 0; nt < 8; nt++)
            #pragma unroll
            for (int j = 0; j < 4; j++) acc[mt][nt][j] = 0.f;

    // prologue prefetch (kt = 0)
    float4 pa0 = *(const float4*)(Xp + 0);
    float4 pa1 = *(const float4*)(Xp + 4);
    float4 pa2 = *(const float4*)(Xp + 8);
    float4 pa3 = *(const float4*)(Xp + 12);
    uint4  pbh0 = *(const uint4*)(Whip + 0);
    uint4  pbh1 = *(const uint4*)(Whip + 8);
    uint4  pbl0 = *(const uint4*)(Wlop + 0);
    uint4  pbl1 = *(const uint4*)(Wlop + 8);

    const int NKT = IN_DIM / 32;   // 16
    for (int kt = 0; kt < NKT; kt++) {
        // ---- convert + store A (16 floats -> hi/lo bf16) ----
        {
            float f[16] = {pa0.x, pa0.y, pa0.z, pa0.w, pa1.x, pa1.y, pa1.z, pa1.w,
                           pa2.x, pa2.y, pa2.z, pa2.w, pa3.x, pa3.y, pa3.z, pa3.w};
            float h[16], l[16];
            #pragma unroll
            for (int i = 0; i < 16; i++) {
                __nv_bfloat16 hb = __float2bfloat16(f[i]);
                h[i] = __bfloat162float(hb);
                l[i] = f[i] - h[i];
            }
            __nv_bfloat16* ah = &Ahi[a_row * ASTRIDE + a_kh];
            __nv_bfloat16* al = &Alo[a_row * ASTRIDE + a_kh];
            #pragma unroll
            for (int q = 0; q < 4; q++) {
                uint2 uh, ul;
                uh.x = pack_bf16x2(h[q*4+0], h[q*4+1]);
                uh.y = pack_bf16x2(h[q*4+2], h[q*4+3]);
                ul.x = pack_bf16x2(l[q*4+0], l[q*4+1]);
                ul.y = pack_bf16x2(l[q*4+2], l[q*4+3]);
                *(uint2*)(ah + q*4) = uh;
                *(uint2*)(al + q*4) = ul;
            }
        }
        // ---- store B (already bf16) ----
        {
            __nv_bfloat16* bh = &Bhi[b_n * ASTRIDE + a_kh];
            __nv_bfloat16* bl = &Blo[b_n * ASTRIDE + a_kh];
            *(uint4*)(bh + 0) = pbh0;
            *(uint4*)(bh + 8) = pbh1;
            *(uint4*)(bl + 0) = pbl0;
            *(uint4*)(bl + 8) = pbl1;
        }
        __syncthreads();

        // ---- prefetch next tile ----
        if (kt + 1 < NKT) {
            const float* xn = Xp + (kt + 1) * 32;
            pa0 = *(const float4*)(xn + 0);
            pa1 = *(const float4*)(xn + 4);
            pa2 = *(const float4*)(xn + 8);
            pa3 = *(const float4*)(xn + 12);
            const __nv_bfloat16* whn = Whip + (kt + 1) * 32;
            const __nv_bfloat16* wln = Wlop + (kt + 1) * 32;
            pbh0 = *(const uint4*)(whn + 0);
            pbh1 = *(const uint4*)(whn + 8);
            pbl0 = *(const uint4*)(wln + 0);
            pbl1 = *(const uint4*)(wln + 8);
        }

        // ---- mma over 2 k16 chunks ----
        const int g  = lane >> 2;
        const int tt = lane & 3;
        #pragma unroll
        for (int kc = 0; kc < 2; kc++) {
            const int gk = kc * 16 + tt * 2;
            uint32_t Afh[2][4], Afl[2][4];
            #pragma unroll
            for (int mt = 0; mt < 2; mt++) {
                const int r = warp_m * 32 + mt * 16 + g;
                Afh[mt][0] = *(const uint32_t*)&Ahi[r * ASTRIDE + gk];
                Afh[mt][1] = *(const uint32_t*)&Ahi[(r + 8) * ASTRIDE + gk];
                Afh[mt][2] = *(const uint32_t*)&Ahi[r * ASTRIDE + gk + 8];
                Afh[mt][3] = *(const uint32_t*)&Ahi[(r + 8) * ASTRIDE + gk + 8];
                Afl[mt][0] = *(const uint32_t*)&Alo[r * ASTRIDE + gk];
                Afl[mt][1] = *(const uint32_t*)&Alo[(r + 8) * ASTRIDE + gk];
                Afl[mt][2] = *(const uint32_t*)&Alo[r * ASTRIDE + gk + 8];
                Afl[mt][3] = *(const uint32_t*)&Alo[(r + 8) * ASTRIDE + gk + 8];
            }
            #pragma unroll
            for (int nt = 0; nt < 8; nt++) {
                const int n = warp_n * 64 + nt * 8 + g;
                uint32_t bh0 = *(const uint32_t*)&Bhi[n * ASTRIDE + gk];
                uint32_t bh1 = *(const uint32_t*)&Bhi[n * ASTRIDE + gk + 8];
                uint32_t bl0 = *(const uint32_t*)&Blo[n * ASTRIDE + gk];
                uint32_t bl1 = *(const uint32_t*)&Blo[n * ASTRIDE + gk + 8];
                #pragma unroll
                for (int mt = 0; mt < 2; mt++) {
                    mma16816(acc[mt][nt], Afh[mt], bh0, bh1);
                    mma16816(acc[mt][nt], Afh[mt], bl0, bl1);
                    mma16816(acc[mt][nt], Afl[mt], bh0, bh1);
                }
            }
        }
        __syncthreads();
    }

    // ---- epilogue: relu + store ----
    {
        const int g  = lane >> 2;
        const int tt = lane & 3;
        #pragma unroll
        for (int mt = 0; mt < 2; mt++) {
            #pragma unroll
            for (int nt = 0; nt < 8; nt++) {
                const int col = warp_n * 64 + nt * 8 + tt * 2;
                const int m0 = bm + warp_m * 32 + mt * 16 + g;
                if (m0 < NN) {
                    float2 v = {fmaxf(acc[mt][nt][0], 0.f), fmaxf(acc[mt][nt][1], 0.f)};
                    *(float2*)&H[(size_t)m0 * HIDDEN + col] = v;
                }
                const int m1 = m0 + 8;
                if (m1 < NN) {
                    float2 v = {fmaxf(acc[mt][nt][2], 0.f), fmaxf(acc[mt][nt][3], 0.f)};
                    *(float2*)&H[(size_t)m1 * HIDDEN + col] = v;
                }
            }
        }
    }
}

// ---------------------------------------------------------------------------
// GEMM2: O = H[N,128] @ W1[128,64]. 64-row tiles, 256 thr, 4x4 microtile.
// Memory-bound (~77MB traffic).
// ---------------------------------------------------------------------------
#define BM2 64
#define HT2_PITCH 132
#define G2_SMEM_FLOATS (HIDDEN * NCLS + BM2 * HT2_PITCH)
#define G2_SMEM_BYTES  (G2_SMEM_FLOATS * 4)

__global__ __launch_bounds__(256)
void gemm2(const float* __restrict__ H, const float* __restrict__ W1,
           float* __restrict__ O)
{
    extern __shared__ float sm2[];
    float* W1s = sm2;                    // [128][64]
    float* Hs  = sm2 + HIDDEN * NCLS;    // [64][132]

    const int tid = threadIdx.x;
    const int bm  = blockIdx.x * BM2;

    {
        const float4* w1v = (const float4*)W1;
        float4* w1sv = (float4*)W1s;
        #pragma unroll
        for (int i = 0; i < 8; i++)
            w1sv[tid + i * 256] = w1v[tid + i * 256];
    }
    #pragma unroll
    for (int j = 0; j < 8; j++) {
        int f = tid + j * 256;
        int row = f >> 5;
        int k4  = (f & 31) * 4;
        int gr = bm + row; if (gr >= NN) gr = NN - 1;
        float4 v = *(const float4*)&H[(size_t)gr * HIDDEN + k4];
        *(float4*)&Hs[row * HT2_PITCH + k4] = v;
    }
    __syncthreads();

    const int tr = tid >> 4;
    const int tc = tid & 15;
    const int r0 = tr * 4;
    const int c0 = tc * 4;

    float acc[4][4];
    #pragma unroll
    for (int i = 0; i < 4; i++)
        #pragma unroll
        for (int j = 0; j < 4; j++) acc[i][j] = 0.f;

    #pragma unroll 4
    for (int k = 0; k < HIDDEN; k += 4) {
        float4 a[4], b[4];
        #pragma unroll
        for (int i = 0; i < 4; i++)
            a[i] = *(const float4*)&Hs[(r0 + i) * HT2_PITCH + k];
        #pragma unroll
        for (int kk = 0; kk < 4; kk++)
            b[kk] = *(const float4*)&W1s[(k + kk) * NCLS + c0];
        #pragma unroll
        for (int i = 0; i < 4; i++) {
            acc[i][0] += a[i].x * b[0].x + a[i].y * b[1].x + a[i].z * b[2].x + a[i].w * b[3].x;
            acc[i][1] += a[i].x * b[0].y + a[i].y * b[1].y + a[i].z * b[2].y + a[i].w * b[3].y;
            acc[i][2] += a[i].x * b[0].z + a[i].y * b[1].z + a[i].z * b[2].z + a[i].w * b[3].z;
            acc[i][3] += a[i].x * b[0].w + a[i].y * b[1].w + a[i].z * b[2].w + a[i].w * b[3].w;
        }
    }

    #pragma unroll
    for (int i = 0; i < 4; i++) {
        const int m = bm + r0 + i;
        if (m < NN) {
            float4 v = {acc[i][0], acc[i][1], acc[i][2], acc[i][3]};
            *(float4*)&O[(size_t)m * NCLS + c0] = v;
        }
    }
}

// ---------------------------------------------------------------------------
// SpMM: y[dst] += val * x[src]. 16 threads/edge, vector red.global.add.v4.f32.
// ---------------------------------------------------------------------------
#define EDGE_ITER 4

__device__ __forceinline__ void red_add_v4(float* addr, float4 v) {
    asm volatile("red.global.add.v4.f32 [%0], {%1,%2,%3,%4};"
                 :: "l"(addr), "f"(v.x), "f"(v.y), "f"(v.z), "f"(v.w)
                 : "memory");
}

__global__ __launch_bounds__(256)
void spmm_kernel(const int* __restrict__ src,
                 const int* __restrict__ dst,
                 const float* __restrict__ val,
                 const float* __restrict__ x,
                 float* __restrict__ y)
{
    const unsigned tid = blockIdx.x * blockDim.x + threadIdx.x;
    const unsigned g = tid >> 4;          // edge group
    const unsigned p = (tid & 15) * 4;    // feature offset
    unsigned e = g * EDGE_ITER;
    #pragma unroll
    for (int it = 0; it < EDGE_ITER; it++, e++) {
        if (e < NEDGE) {
            const int   s = __ldg(src + e);
            const int   d = __ldg(dst + e);
            const float v = __ldg(val + e);
            float4 xv = *(const float4*)(x + (size_t)s * NCLS + p);
            xv.x *= v; xv.y *= v; xv.z *= v; xv.w *= v;
            red_add_v4(y + (size_t)d * NCLS + p, xv);
        }
    }
}

// ---------------------------------------------------------------------------
extern "C" void kernel_launch(void* const* d_in, const int* in_sizes, int n_in,
                              void* d_out, int out_size)
{
    const float* X  = (const float*)d_in[0];
    const float* W0 = (const float*)d_in[1];
    const float* W1 = (const float*)d_in[2];
    const float* ev = (const float*)d_in[3];
    const int*   es = (const int*)d_in[4];
    const int*   ed = (const int*)d_in[5];
    float* out = (float*)d_out;

    float *h, *bufA, *bufB;
    __nv_bfloat16 *whi, *wlo;
    cudaGetSymbolAddress((void**)&h,    g_h);
    cudaGetSymbolAddress((void**)&bufA, g_bufA);
    cudaGetSymbolAddress((void**)&bufB, g_bufB);
    cudaGetSymbolAddress((void**)&whi,  g_w0hi);
    cudaGetSymbolAddress((void**)&wlo,  g_w0lo);

    cudaFuncSetAttribute(gemm2, cudaFuncAttributeMaxDynamicSharedMemorySize,
                         G2_SMEM_BYTES);

    const size_t feat_bytes = (size_t)NN * NCLS * sizeof(float);
    const int spmm_grid = (int)(((size_t)NEDGE * 16) / (256 * EDGE_ITER)); // 50000

    // zero accumulators up front (independent of dense phase)
    cudaMemsetAsync(bufB, 0, feat_bytes);
    cudaMemsetAsync(out, 0, feat_bytes);

    // dense phase
    w0_conv<<<(IN_DIM * HIDDEN) / 256, 256>>>(W0);
    gemm1_mma<<<(NN + 127) / 128, 256>>>(X, whi, wlo, h);
    gemm2<<<(NN + BM2 - 1) / BM2, 256, G2_SMEM_BYTES>>>(h, W1, bufA);

    // graph phase
    spmm_kernel<<<spmm_grid, 256>>>(es, ed, ev, bufA, bufB);
    spmm_kernel<<<spmm_grid, 256>>>(es, ed, ev, bufB, out);
}